// round 3
// baseline (speedup 1.0000x reference)
#include <cuda_runtime.h>

// CRF NLL: B=1024, T=4096, K=16
// d_in[0]=feats [B,T,K] f32, d_in[1]=tags [B,T] i32, d_in[2]=transitions [K,K] f32
// out: [B] f32

#define T_LEN 4096
#define KTAG 16
#define TILE 16
#define START_TAG 14
#define STOP_TAG 15

__device__ __forceinline__ float4 lds128v(unsigned addr) {
    float4 v;
    asm volatile("ld.volatile.shared.v4.f32 {%0,%1,%2,%3}, [%4];"
                 : "=f"(v.x), "=f"(v.y), "=f"(v.z), "=f"(v.w) : "r"(addr));
    return v;
}
__device__ __forceinline__ void sts32v(unsigned addr, float v) {
    asm volatile("st.volatile.shared.f32 [%0], %1;" :: "r"(addr), "f"(v) : "memory");
}

__global__ __launch_bounds__(128, 1)
void crf_nll_kernel(const float* __restrict__ feats,
                    const int* __restrict__ tags,
                    const float* __restrict__ trans,
                    float* __restrict__ out) {
    __shared__ float sExpT[256];   // exp(trans[j][i])
    __shared__ float sLogT[256];   // trans[j][i]
    __shared__ float sP[8][16];    // per-element probability vector

    int tid = threadIdx.x;
    for (int i = tid; i < 256; i += 128) {
        float tv = trans[i];
        sLogT[i] = tv;
        sExpT[i] = __expf(tv);     // exp(-10000) -> 0: correct masking
    }

    int lane = tid & 31;
    int grp  = lane >> 4;          // 2 batch elements per warp
    int j    = lane & 15;          // this thread owns state j
    int warp = tid >> 5;
    int g    = warp * 2 + grp;
    int b    = blockIdx.x * 8 + g;

    __syncthreads();

    float Mr[16];
    #pragma unroll
    for (int i = 0; i < 16; i++) Mr[i] = sExpT[j * 16 + i];
    float Mstop = sExpT[STOP_TAG * 16 + j];

    const float* fbase = feats + (size_t)b * T_LEN * KTAG;
    const int*   tptr  = tags  + (size_t)b * T_LEN;

    unsigned pBase = (unsigned)__cvta_generic_to_shared(&sP[g][0]);
    unsigned pSelf = pBase + j * 4;

    sP[g][j] = (j == START_TAG) ? 1.0f : 0.0f;
    __syncthreads();

    int   esum = 0;          // exact power-of-2 scale accumulator
    float gold = 0.0f;
    int   prevtag = START_TAG;
    float pnew = 0.0f;
    float stale_m = 1.0f;    // max measured 2 steps before it is applied

    float eA[TILE], eB[TILE];  // precomputed exp(feat) for own state
    int   gA[TILE], gB[TILE];

    // prime first tile: exp at prefetch time (off the scan chain)
    #pragma unroll
    for (int u = 0; u < TILE; u++) eA[u] = __expf(fbase[u * KTAG + j]);
    {
        const int4* tp4 = reinterpret_cast<const int4*>(tptr);
        #pragma unroll
        for (int q = 0; q < 4; q++) {
            int4 v = tp4[q];
            gA[4*q+0] = v.x; gA[4*q+1] = v.y; gA[4*q+2] = v.z; gA[4*q+3] = v.w;
        }
    }

    const int NT = T_LEN / TILE;   // 256
    #pragma unroll 1
    for (int tile = 0; tile < NT; tile++) {
        if (tile + 1 < NT) {
            int base = (tile + 1) * TILE;
            #pragma unroll
            for (int u = 0; u < TILE; u++) eB[u] = __expf(fbase[(base + u) * KTAG + j]);
            const int4* tp4 = reinterpret_cast<const int4*>(tptr + base);
            #pragma unroll
            for (int q = 0; q < 4; q++) {
                int4 v = tp4[q];
                gB[4*q+0] = v.x; gB[4*q+1] = v.y; gB[4*q+2] = v.z; gB[4*q+3] = v.w;
            }
        }
        int tbase = tile * TILE;

        #pragma unroll
        for (int u = 0; u < TILE; u++) {
            float ef = eA[u];
            int   tg = gA[u];

            // apply stale renorm (scale known well in advance -> off chain)
            if ((u & 3) == 3) {
                int e = (__float_as_int(stale_m) >> 23) & 255;
                ef *= __int_as_float((254 - e) << 23);   // * 2^(127-e), exact
                esum += e - 127;
            }

            // broadcast p: conflict-free volatile LDS.128 x4 (no syncwarp:
            // 16-lane group is convergent, smem ops retire in issue order)
            float4 q0 = lds128v(pBase);
            float4 q1 = lds128v(pBase + 16);
            float4 q2 = lds128v(pBase + 32);
            float4 q3 = lds128v(pBase + 48);

            // measure max (consumed 2 steps later; FMNMX tree off chain)
            if ((u & 3) == 1) {
                float m0 = fmaxf(fmaxf(q0.x, q0.y), fmaxf(q0.z, q0.w));
                float m1 = fmaxf(fmaxf(q1.x, q1.y), fmaxf(q1.z, q1.w));
                float m2 = fmaxf(fmaxf(q2.x, q2.y), fmaxf(q2.z, q2.w));
                float m3 = fmaxf(fmaxf(q3.x, q3.y), fmaxf(q3.z, q3.w));
                stale_m = fmaxf(fmaxf(m0, m1), fmaxf(m2, m3));
            }

            // s_j = sum_i M[j,i] * p_i ; tail FMA depends only on last quad
            float a0 = fmaf(q3.x, Mr[12], fmaf(q2.x, Mr[ 8], fmaf(q1.x, Mr[4], q0.x * Mr[0])));
            float a1 = fmaf(q3.y, Mr[13], fmaf(q2.y, Mr[ 9], fmaf(q1.y, Mr[5], q0.y * Mr[1])));
            float a2 = fmaf(q3.z, Mr[14], fmaf(q2.z, Mr[10], fmaf(q1.z, Mr[6], q0.z * Mr[2])));
            float a3 = fmaf(q3.w, Mr[15], fmaf(q2.w, Mr[11], fmaf(q1.w, Mr[7], q0.w * Mr[3])));
            pnew = ((a0 + a1) + (a2 + a3)) * ef;
            sts32v(pSelf, pnew);

            // gold score (uniform L1-hot gather + smem lookup, off chain)
            gold += fbase[(tbase + u) * KTAG + tg] + sLogT[tg * 16 + prevtag];
            prevtag = tg;
        }

        #pragma unroll
        for (int u = 0; u < TILE; u++) { eA[u] = eB[u]; gA[u] = gB[u]; }
    }

    // forward_score = esum*ln2 + log( sum_j exp(trans[STOP,j]) * p_j )
    float v = Mstop * pnew;
    v += __shfl_xor_sync(0xffffffffu, v, 1, 16);
    v += __shfl_xor_sync(0xffffffffu, v, 2, 16);
    v += __shfl_xor_sync(0xffffffffu, v, 4, 16);
    v += __shfl_xor_sync(0xffffffffu, v, 8, 16);

    double fwd = (double)esum * 0.6931471805599453 + (double)__logf(v);
    float goldT = gold + sLogT[STOP_TAG * 16 + prevtag];

    if (j == 0) out[b] = (float)(fwd - (double)goldT);
}

extern "C" void kernel_launch(void* const* d_in, const int* in_sizes, int n_in,
                              void* d_out, int out_size) {
    const float* feats = (const float*)d_in[0];
    const int*   tags  = (const int*)d_in[1];
    const float* trans = (const float*)d_in[2];
    float* out = (float*)d_out;

    int B = in_sizes[1] / T_LEN;           // 1024
    int blocks = B / 8;
    crf_nll_kernel<<<blocks, 128>>>(feats, tags, trans, out);
}